// round 13
// baseline (speedup 1.0000x reference)
#include <cuda_runtime.h>
#include <cuda_bf16.h>
#include <cuda_fp16.h>
#include <math.h>
#include <stdint.h>

#define B_ 64
#define L_ 2048
#define H_ 512
#define A_ 128
#define LN_EPS 1e-3f
#define KCH 32

#if defined(__CUDA_ARCH__) && defined(__CUDA_ARCH_FEAT_SM103_ALL)
#define HAS_TC 1
#else
#define HAS_TC 0
#endif

// min-blocks 4: 64-reg budget fits the tcgen05.ld.x32 contiguous window (5 -> 48 regs did not)
#define GEMM_MINB 4

// ---------------- device scratch ----------------
__device__ __half g_hatt_h[B_ * L_ * A_];
__device__ float g_context[B_ * H_];
__device__ float g_u[B_ * A_];
__device__ float g_scores[B_ * L_];
__device__ float g_attended[B_ * H_];
__device__ __align__(16) unsigned short g_Whi[8 * 8192];
__device__ __align__(16) unsigned short g_Wlo[8 * 8192];

// ---------------- generic helpers ----------------
__device__ __forceinline__ uint32_t smem_u32(const void* p) {
    uint32_t a;
    asm("{ .reg .u64 t; cvta.to.shared.u64 t, %1; cvt.u32.u64 %0, t; }" : "=r"(a) : "l"(p));
    return a;
}
__device__ __forceinline__ unsigned long long pack2(float lo, float hi) {
    unsigned long long r;
    asm("mov.b64 %0, {%1,%2};" : "=l"(r) : "f"(lo), "f"(hi));
    return r;
}
__device__ __forceinline__ void unpack2(unsigned long long v, float& lo, float& hi) {
    asm("mov.b64 {%0,%1}, %2;" : "=f"(lo), "=f"(hi) : "l"(v));
}
#define FMA2(c, a, b) asm("fma.rn.f32x2 %0, %1, %2, %0;" : "+l"(c) : "l"(a), "l"(b))
#define SWZ128(off) ((off) ^ (((off) >> 3) & 0x70))

__device__ __forceinline__ float tanh_hw(float x) {
    float r;
    asm("tanh.approx.f32 %0, %1;" : "=f"(r) : "f"(x));
    return r;
}
#define WARPSUM(s) do { \
    s += __shfl_xor_sync(0xffffffffu, s, 16); \
    s += __shfl_xor_sync(0xffffffffu, s, 8); \
    s += __shfl_xor_sync(0xffffffffu, s, 4); \
    s += __shfl_xor_sync(0xffffffffu, s, 2); \
    s += __shfl_xor_sync(0xffffffffu, s, 1); \
} while (0)

#define CP_ASYNC16(dst_smem, src_gptr) \
    asm volatile("cp.async.cg.shared.global [%0], [%1], 16;" \
                 :: "r"((uint32_t)(dst_smem)), "l"(src_gptr) : "memory")
#define CP_ASYNC_COMMIT() asm volatile("cp.async.commit_group;" ::: "memory")
#define CP_ASYNC_WAIT_ALL() asm volatile("cp.async.wait_group 0;" ::: "memory")

// ---------------- tcgen05 helpers ----------------
#define MBARRIER_INIT(addr, cnt) \
    asm volatile("mbarrier.init.shared.b64 [%0], %1;" :: "r"((uint32_t)(addr)), "r"((uint32_t)(cnt)) : "memory")
#define MBARRIER_INVAL(addr) \
    asm volatile("mbarrier.inval.shared.b64 [%0];" :: "r"((uint32_t)(addr)) : "memory")
#define MBARRIER_WAIT_PARITY(mbar_smem_addr, phase_parity) do { \
    uint32_t _mbar = (uint32_t)(mbar_smem_addr); \
    uint32_t _parity = (uint32_t)(phase_parity); \
    uint32_t _done; \
    asm volatile( \
        "{\n\t.reg .pred p;\n\t" \
        "mbarrier.try_wait.parity.acquire.cta.shared::cta.b64 p, [%1], %2;\n\t" \
        "selp.b32 %0, 1, 0, p;\n\t}" \
        : "=r"(_done) : "r"(_mbar), "r"(_parity) : "memory"); \
    if (!_done) { \
        asm volatile( \
            "{\n\t.reg .pred P1;\n\t" \
            "WAIT_LOOP_%=:\n\t" \
            "mbarrier.try_wait.parity.acquire.cta.shared::cta.b64 P1, [%0], %1, 0x989680;\n\t" \
            "@P1 bra.uni WAIT_DONE_%=;\n\t" \
            "bra.uni WAIT_LOOP_%=;\n\t" \
            "WAIT_DONE_%=:\n\t}" \
            :: "r"(_mbar), "r"(_parity) : "memory"); \
    } \
} while(0)
#define TCGEN05_ALLOC(smem_res, nCols) \
    asm volatile("tcgen05.alloc.cta_group::1.sync.aligned.shared::cta.b32 [%0], %1;" \
                 :: "r"((uint32_t)(smem_res)), "r"((uint32_t)(nCols)) : "memory")
#define TCGEN05_DEALLOC(tmem, nCols) \
    asm volatile("tcgen05.dealloc.cta_group::1.sync.aligned.b32 %0, %1;" :: "r"(tmem), "r"((uint32_t)(nCols)))
#define TCGEN05_RELINQ() \
    asm volatile("tcgen05.relinquish_alloc_permit.cta_group::1.sync.aligned;")
#define TCGEN05_COMMIT(mbar) \
    asm volatile("tcgen05.commit.cta_group::1.mbarrier::arrive::one.shared::cluster.b64 [%0];" \
                 :: "r"((uint32_t)(mbar)) : "memory")
#define TCGEN05_WAIT_LD() asm volatile("tcgen05.wait::ld.sync.aligned;" ::: "memory")
#define TCGEN05_WAIT_ST() asm volatile("tcgen05.wait::st.sync.aligned;" ::: "memory")
#define TCGEN05_FENCE_AFTER() asm volatile("tcgen05.fence::after_thread_sync;" ::: "memory")
#define TCGEN05_FENCE_BEFORE() asm volatile("tcgen05.fence::before_thread_sync;" ::: "memory")
#define FENCE_PROXY_ASYNC() asm volatile("fence.proxy.async.shared::cta;" ::: "memory")
#define TCGEN05_LD_32X32B_X32(r, tmem_addr) \
    asm volatile( \
        "tcgen05.ld.sync.aligned.32x32b.x32.b32 " \
        "{%0, %1, %2, %3, %4, %5, %6, %7, " \
        " %8, %9, %10, %11, %12, %13, %14, %15, " \
        " %16, %17, %18, %19, %20, %21, %22, %23, " \
        " %24, %25, %26, %27, %28, %29, %30, %31}, [%32];" \
        : "=r"((r)[0]),  "=r"((r)[1]),  "=r"((r)[2]),  "=r"((r)[3]), \
          "=r"((r)[4]),  "=r"((r)[5]),  "=r"((r)[6]),  "=r"((r)[7]), \
          "=r"((r)[8]),  "=r"((r)[9]),  "=r"((r)[10]), "=r"((r)[11]), \
          "=r"((r)[12]), "=r"((r)[13]), "=r"((r)[14]), "=r"((r)[15]), \
          "=r"((r)[16]), "=r"((r)[17]), "=r"((r)[18]), "=r"((r)[19]), \
          "=r"((r)[20]), "=r"((r)[21]), "=r"((r)[22]), "=r"((r)[23]), \
          "=r"((r)[24]), "=r"((r)[25]), "=r"((r)[26]), "=r"((r)[27]), \
          "=r"((r)[28]), "=r"((r)[29]), "=r"((r)[30]), "=r"((r)[31]) \
        : "r"(tmem_addr))
#define TCGEN05_ST_32X32B_X8(tmem_addr, r) \
    asm volatile( \
        "tcgen05.st.sync.aligned.32x32b.x8.b32 [%0], " \
        "{%1, %2, %3, %4, %5, %6, %7, %8};" \
        :: "r"(tmem_addr), \
           "r"((r)[0]), "r"((r)[1]), "r"((r)[2]), "r"((r)[3]), \
           "r"((r)[4]), "r"((r)[5]), "r"((r)[6]), "r"((r)[7]) \
        : "memory")

static constexpr uint64_t SMEM_DESC_BASE_SW128 =
    (uint64_t(2) << 61) | (uint64_t(1) << 46) | (uint64_t(64) << 32) | (uint64_t(1) << 16);
#define MAKE_SMEM_DESC(base) (SMEM_DESC_BASE_SW128 | ((uint64_t)((base) >> 4) & 0x3FFF))
#define IDESC_BF16_M128_N128 0x8200490u

#if HAS_TC
__device__ __forceinline__ void mma_f16_ts_cg1(uint32_t d_tmem, uint32_t a_tmem,
                                               uint64_t b_desc, uint32_t idesc, uint32_t en) {
    asm volatile(
        "{\n\t.reg .pred p;\n\t"
        "setp.ne.u32 p, %4, 0;\n\t"
        "tcgen05.mma.cta_group::1.kind::f16 [%0], [%1], %2, %3, {%5, %5, %5, %5}, p;\n\t}"
        :: "r"(d_tmem), "r"(a_tmem), "l"(b_desc), "r"(idesc), "r"(en), "r"(0u)
        : "memory");
}
#endif

// ---------------- smem layout (TS GEMM: 33792 B) ----------------
#define SM_TMEM 0
#define SM_MBAR 8
#define SM_CTX  64                      // 64 floats
#define SM_WHI  1024                    // 16 KB
#define SM_WLO  (1024 + 16384)          // 16 KB
#define SM_TOTAL (1024 + 2 * 16384)     // 33792

// TMEM layout: D cols 0-127, A-hi 128-159, A-lo 160-191; alloc 256
#define TM_D   0
#define TM_AHI 128
#define TM_ALO 160

// ---------------- kernel 0: zero accumulators ----------------
__global__ void k_zero() {
    int i = blockIdx.x * blockDim.x + threadIdx.x;
    if (i < B_ * H_) {
        g_context[i] = 0.f;
        g_attended[i] = 0.f;
    }
}

// ---------------- kernel 1: W -> bf16 hi/lo pre-swizzled tiles ----------------
__global__ void k_wprep(const float* __restrict__ W) {
    int i = blockIdx.x * blockDim.x + threadIdx.x;
    int c = i >> 13;
    int rem = i & 8191;
    int n = rem >> 6;
    int kk = rem & 63;
    float x = W[(size_t)(c * 64 + kk) * A_ + n];
    __nv_bfloat16 hi = __float2bfloat16(x);
    float hif = __bfloat162float(hi);
    __nv_bfloat16 lo = __float2bfloat16(x - hif);
    uint32_t off = n * 128 + kk * 2;
    uint32_t sw = SWZ128(off);
    g_Whi[c * 8192 + (sw >> 1)] = __bfloat16_as_ushort(hi);
    g_Wlo[c * 8192 + (sw >> 1)] = __bfloat16_as_ushort(lo);
}

// ---------------- kernel 2: warm (keeps k_gemm at profiled launch idx 3) ----------------
__global__ void k_warm() {
    int i = blockIdx.x * blockDim.x + threadIdx.x;
    if (i < B_ * L_) g_scores[i] = 0.f;
}

// ---------------- kernel 3: GEMM hatt = hidden @ W (TS mode: A in TMEM) ----------------
__global__ __launch_bounds__(256, GEMM_MINB) void k_gemm(const float* __restrict__ hid,
                                                         const float* __restrict__ W) {
    extern __shared__ char smem[];
#if HAS_TC
    const uint32_t smem_base = smem_u32(smem);
    const int tid = threadIdx.x;
    const int wid = tid >> 5;
    const int lid = tid & 31;
    const int b = blockIdx.y;
    const int l0 = blockIdx.x * 128;

    float* ctxs = (float*)(smem + SM_CTX);

    if (wid == 0) {
        TCGEN05_ALLOC(smem_base + SM_TMEM, 256);
        TCGEN05_RELINQ();
    }
    if (tid == 0) MBARRIER_INIT(smem_base + SM_MBAR, 1);
    if (tid < 64) ctxs[tid] = 0.f;
    __syncthreads();

    uint32_t tmem_base;
    asm volatile("ld.shared.b32 %0, [%1];" : "=r"(tmem_base) : "r"(smem_base + SM_TMEM));

    const uint64_t wh_desc = MAKE_SMEM_DESC(smem_base + SM_WHI);
    const uint64_t wl_desc = MAKE_SMEM_DESC(smem_base + SM_WLO);

    // thread role: row = (wid&3)*32 + lane; k-half h = wid>>2 (32 k's = 16 bf16x2 cols)
    const int row = ((wid & 3) << 5) + lid;
    const int h = wid >> 2;
    const uint32_t warp_off = ((uint32_t)((tid & 127) >> 5)) << 21;
    const float* Arow = hid + ((size_t)(b * L_ + l0 + row)) * H_ + h * 32;

    for (int kc = 0; kc < 8; kc++) {
        const int k0 = kc * 64;

        // W chunk via cp.async (hides under convert)
        {
            const char* wh = (const char*)(g_Whi + (size_t)kc * 8192);
            const char* wl = (const char*)(g_Wlo + (size_t)kc * 8192);
#pragma unroll
            for (int p = 0; p < 4; p++) {
                const uint32_t o = (uint32_t)(p * 256 + tid) * 16;
                CP_ASYNC16(smem_base + SM_WHI + o, wh + o);
                CP_ASYNC16(smem_base + SM_WLO + o, wl + o);
            }
            CP_ASYNC_COMMIT();
        }

        // A: this thread's 32 fp32 of row `row`, k in [k0+h*32, +32) -> TMEM bf16x2 hi/lo
        const float4* Af = (const float4*)(Arow + k0);
#pragma unroll
        for (int half = 0; half < 2; half++) {
            uint32_t hi2[8], lo2[8];
#pragma unroll
            for (int q = 0; q < 4; q++) {
                const float4 v = Af[half * 4 + q];
                float s0 = v.x, s1 = v.y, s2 = v.z, s3 = v.w;
                WARPSUM(s0); WARPSUM(s1); WARPSUM(s2); WARPSUM(s3);
                if (lid == 0) {
                    const int jb = h * 32 + half * 16 + q * 4;
                    atomicAdd(&ctxs[jb + 0], s0);
                    atomicAdd(&ctxs[jb + 1], s1);
                    atomicAdd(&ctxs[jb + 2], s2);
                    atomicAdd(&ctxs[jb + 3], s3);
                }
                uint32_t ha, hb, la, lb;
                asm("cvt.rn.bf16x2.f32 %0, %1, %2;" : "=r"(ha) : "f"(v.y), "f"(v.x));
                const float f0 = __uint_as_float(ha << 16);
                const float f1 = __uint_as_float(ha & 0xffff0000u);
                asm("cvt.rn.bf16x2.f32 %0, %1, %2;" : "=r"(la) : "f"(v.y - f1), "f"(v.x - f0));
                asm("cvt.rn.bf16x2.f32 %0, %1, %2;" : "=r"(hb) : "f"(v.w), "f"(v.z));
                const float f2 = __uint_as_float(hb << 16);
                const float f3 = __uint_as_float(hb & 0xffff0000u);
                asm("cvt.rn.bf16x2.f32 %0, %1, %2;" : "=r"(lb) : "f"(v.w - f3), "f"(v.z - f2));
                hi2[q * 2] = ha; hi2[q * 2 + 1] = hb;
                lo2[q * 2] = la; lo2[q * 2 + 1] = lb;
            }
            const uint32_t col = (uint32_t)(h * 16 + half * 8);
            TCGEN05_ST_32X32B_X8(tmem_base + TM_AHI + col + warp_off, hi2);
            TCGEN05_ST_32X32B_X8(tmem_base + TM_ALO + col + warp_off, lo2);
            TCGEN05_WAIT_ST();
        }

        CP_ASYNC_WAIT_ALL();
        FENCE_PROXY_ASYNC();
        TCGEN05_FENCE_BEFORE();
        __syncthreads();

        // 12 MMAs (4 K=16 steps x {hi*hi, hi*lo, lo*hi}), TS mode
        if (wid == 0) {
            uint32_t one;
            asm volatile("{\n\t.reg .pred p;\n\telect.sync _|p, 0xFFFFFFFF;\n\tselp.b32 %0, 1, 0, p;\n\t}" : "=r"(one));
            if (one) {
                TCGEN05_FENCE_AFTER();
#pragma unroll
                for (int s = 0; s < 4; s++) {
                    const uint64_t ds = (uint64_t)(2 * s);
                    const uint32_t ao = (uint32_t)(s * 8);
                    mma_f16_ts_cg1(tmem_base + TM_D, tmem_base + TM_AHI + ao, wh_desc + ds,
                                   IDESC_BF16_M128_N128, (kc == 0 && s == 0) ? 0u : 1u);
                    mma_f16_ts_cg1(tmem_base + TM_D, tmem_base + TM_AHI + ao, wl_desc + ds,
                                   IDESC_BF16_M128_N128, 1u);
                    mma_f16_ts_cg1(tmem_base + TM_D, tmem_base + TM_ALO + ao, wh_desc + ds,
                                   IDESC_BF16_M128_N128, 1u);
                }
                TCGEN05_COMMIT(smem_base + SM_MBAR);
            }
        }

        // flush ctx partials while MMA drains, then gate next chunk on completion
        if (tid < 64) {
            float v = ctxs[tid];
            ctxs[tid] = 0.f;
            atomicAdd(&g_context[b * H_ + k0 + tid], v);
        }
        MBARRIER_WAIT_PARITY(smem_base + SM_MBAR, kc & 1);
        __syncthreads();
    }

    TCGEN05_FENCE_AFTER();

    // epilogue: TMEM D -> padded smem slab -> fp16 half2-packed coalesced gmem
    float* slab = (float*)(smem + SM_WHI);  // overlays dead W buffers
    uint32_t* Cb = (uint32_t*)(g_hatt_h + ((size_t)b * L_ + l0) * A_);
    for (int cb = 0; cb < 4; cb++) {
        if (wid < 4) {
            uint32_t r[32];
            TCGEN05_LD_32X32B_X32(r, tmem_base + TM_D + cb * 32);
            TCGEN05_WAIT_LD();
            const int rrow = wid * 32 + lid;
#pragma unroll
            for (int j = 0; j < 32; j++) slab[rrow * 33 + j] = __uint_as_float(r[j]);
        }
        __syncthreads();
#pragma unroll
        for (int it = 0; it < 8; it++) {
            const int idx = it * 256 + tid;
            const int rrow = idx >> 4;
            const int c2 = idx & 15;
            __half2 hh = __floats2half2_rn(slab[rrow * 33 + c2 * 2], slab[rrow * 33 + c2 * 2 + 1]);
            Cb[(size_t)rrow * (A_ / 2) + cb * 16 + c2] = *(uint32_t*)&hh;
        }
        __syncthreads();
    }

    TCGEN05_FENCE_BEFORE();
    if (tid == 0) MBARRIER_INVAL(smem_base + SM_MBAR);
    __syncthreads();
    if (wid == 0) TCGEN05_DEALLOC(tmem_base, 256);

#else  // ---------------- FFMA2 fallback ----------------
    float* As = (float*)smem;
    float* Bs = As + KCH * 128;

    const int tile = blockIdx.x;
    const int b = blockIdx.y;
    const int l0 = tile * 128;
    const int tid = threadIdx.x;
    const int tx = tid & 15, ty = tid >> 4;
    const int c0 = tx * 8, r0 = ty * 8;

    unsigned long long acc[8][4];
#pragma unroll
    for (int i = 0; i < 8; i++)
#pragma unroll
        for (int j = 0; j < 4; j++) acc[i][j] = 0ULL;

    const float* Abase = hid + ((size_t)(b * L_ + l0)) * H_;

    for (int kc = 0; kc < H_ / KCH; kc++) {
        const int k0 = kc * KCH;
#pragma unroll
        for (int p = 0; p < 4; p++) {
            int f4 = p * 256 + tid;
            int row = f4 >> 3;
            int kq = f4 & 7;
            float4 v = *(const float4*)(Abase + (size_t)row * H_ + k0 + kq * 4);
            As[(kq * 4 + 0) * 128 + row] = v.x;
            As[(kq * 4 + 1) * 128 + row] = v.y;
            As[(kq * 4 + 2) * 128 + row] = v.z;
            As[(kq * 4 + 3) * 128 + row] = v.w;
        }
#pragma unroll
        for (int p = 0; p < 4; p++) {
            int f4 = p * 256 + tid;
            int kk = f4 >> 5;
            int c4 = f4 & 31;
            *(float4*)&Bs[kk * 128 + c4 * 4] = *(const float4*)(W + (size_t)(k0 + kk) * A_ + c4 * 4);
        }
        __syncthreads();

        if (tid < 32) {
            float s = 0.f;
#pragma unroll 8
            for (int r = 0; r < 128; r++) s += As[tid * 128 + ((r + tid) & 127)];
            atomicAdd(&g_context[b * H_ + k0 + tid], s);
        }

#pragma unroll 8
        for (int kk = 0; kk < KCH; kk++) {
            float4 a0 = *(const float4*)&As[kk * 128 + r0];
            float4 a1 = *(const float4*)&As[kk * 128 + r0 + 4];
            ulonglong2 b01 = *(const ulonglong2*)&Bs[kk * 128 + c0];
            ulonglong2 b23 = *(const ulonglong2*)&Bs[kk * 128 + c0 + 4];
            unsigned long long bb0 = b01.x, bb1 = b01.y, bb2 = b23.x, bb3 = b23.y;
            float av[8] = {a0.x, a0.y, a0.z, a0.w, a1.x, a1.y, a1.z, a1.w};
#pragma unroll
            for (int i = 0; i < 8; i++) {
                unsigned long long ap = pack2(av[i], av[i]);
                FMA2(acc[i][0], ap, bb0);
                FMA2(acc[i][1], ap, bb1);
                FMA2(acc[i][2], ap, bb2);
                FMA2(acc[i][3], ap, bb3);
            }
        }
        __syncthreads();
    }

    __half* Cbase = g_hatt_h + ((size_t)(b * L_ + l0 + r0)) * A_ + c0;
#pragma unroll
    for (int i = 0; i < 8; i++) {
        float o[8];
#pragma unroll
        for (int j = 0; j < 4; j++) unpack2(acc[i][j], o[2 * j], o[2 * j + 1]);
#pragma unroll
        for (int j = 0; j < 8; j++) Cbase[(size_t)i * A_ + j] = __float2half_rn(o[j]);
    }
#endif
}

// ---------------- kernel 4: u[b][a] = (mean context) @ U_a ----------------
__global__ __launch_bounds__(512) void k_uatt(const float* __restrict__ U) {
    const int b = blockIdx.x;
    const int tid = threadIdx.x;
    const int a = tid & 127;
    const int q = tid >> 7;
    __shared__ float c[H_];
    __shared__ float part[4][128];
    c[tid] = g_context[b * H_ + tid] * (1.f / (float)L_);
    __syncthreads();
    const float* Up = U + (size_t)(q * 128) * A_ + a;
    const float* cp = c + q * 128;
    float s0 = 0.f, s1 = 0.f, s2 = 0.f, s3 = 0.f;
#pragma unroll 8
    for (int hh = 0; hh < 128; hh += 4) {
        s0 += cp[hh] * Up[(size_t)hh * A_];
        s1 += cp[hh + 1] * Up[(size_t)(hh + 1) * A_];
        s2 += cp[hh + 2] * Up[(size_t)(hh + 2) * A_];
        s3 += cp[hh + 3] * Up[(size_t)(hh + 3) * A_];
    }
    part[q][a] = (s0 + s1) + (s2 + s3);
    __syncthreads();
    if (tid < 128) {
        g_u[b * A_ + tid] = (part[0][tid] + part[1][tid]) + (part[2][tid] + part[3][tid]);
    }
}

// ---------------- kernel 5: scores = v^T tanh_hw(hatt_fp16 + u), MLP=16 ----------------
__global__ __launch_bounds__(256) void k_scores(const float* __restrict__ va) {
    __shared__ float su[A_], sv[A_];
    const int tile = blockIdx.x, b = blockIdx.y;
    const int tid = threadIdx.x;
    if (tid < A_) {
        su[tid] = g_u[b * A_ + tid];
        sv[tid] = va[tid];
    }
    __syncthreads();
    const int w = tid >> 5, lane = tid & 31;
    const float4 u4 = *(const float4*)&su[lane * 4];
    const float4 v4 = *(const float4*)&sv[lane * 4];

    uint2 hraw[16];
    const uint32_t* base =
        (const uint32_t*)(g_hatt_h + ((size_t)(b * L_ + tile * 128 + w * 16)) * A_) + lane * 2;
#pragma unroll
    for (int t = 0; t < 16; t++)
        hraw[t] = *(const uint2*)(base + (size_t)t * (A_ / 2));

#pragma unroll
    for (int t = 0; t < 16; t++) {
        const float2 h01 = __half22float2(*(const __half2*)&hraw[t].x);
        const float2 h23 = __half22float2(*(const __half2*)&hraw[t].y);
        float s = v4.x * tanh_hw(h01.x + u4.x) + v4.y * tanh_hw(h01.y + u4.y) +
                  v4.z * tanh_hw(h23.x + u4.z) + v4.w * tanh_hw(h23.y + u4.w);
#pragma unroll
        for (int o = 16; o; o >>= 1) s += __shfl_down_sync(0xffffffffu, s, o);
        if (lane == 0) g_scores[b * L_ + tile * 128 + w * 16 + t] = s;
    }
}

// ---------------- kernel 6: softmax over L, write attn to d_out ----------------
__global__ void k_softmax(float* __restrict__ attn_out) {
    const int b = blockIdx.x;
    const int tid = threadIdx.x;
    __shared__ float red[256];
    float vals[8];
    float m = -1e30f;
#pragma unroll
    for (int i = 0; i < 8; i++) {
        vals[i] = g_scores[b * L_ + tid + 256 * i];
        m = fmaxf(m, vals[i]);
    }
    red[tid] = m;
    __syncthreads();
    for (int o = 128; o; o >>= 1) {
        if (tid < o) red[tid] = fmaxf(red[tid], red[tid + o]);
        __syncthreads();
    }
    m = red[0];
    __syncthreads();
    float sum = 0.f;
#pragma unroll
    for (int i = 0; i < 8; i++) {
        vals[i] = __expf(vals[i] - m);
        sum += vals[i];
    }
    red[tid] = sum;
    __syncthreads();
    for (int o = 128; o; o >>= 1) {
        if (tid < o) red[tid] += red[tid + o];
        __syncthreads();
    }
    const float inv = 1.f / red[0];
#pragma unroll
    for (int i = 0; i < 8; i++) attn_out[b * L_ + tid + 256 * i] = vals[i] * inv;
}

// ---------------- kernel 7: attended ----------------
__global__ __launch_bounds__(512) void k_attended(const float* __restrict__ hid,
                                                  const float* __restrict__ attn) {
    const int tile = blockIdx.x, b = blockIdx.y;
    const int tid = threadIdx.x;
    const int g = tid >> 7;
    const int h4 = tid & 127;
    __shared__ float sa[128];
    __shared__ float4 comb[4][128];
    if (tid < 128) sa[tid] = attn[b * L_ + tile * 128 + tid];
    __syncthreads();
    const float4* hp = (const float4*)(hid + ((size_t)(b * L_) + tile * 128 + g * 32) * H_) + h4;
    const float* sap = sa + g * 32;
    float4 acc = {0.f, 0.f, 0.f, 0.f};
#pragma unroll 4
    for (int l = 0; l < 32; l++) {
        const float w = sap[l];
        const float4 v = hp[(size_t)l * (H_ / 4)];
        acc.x += w * v.x;
        acc.y += w * v.y;
        acc.z += w * v.z;
        acc.w += w * v.w;
    }
    comb[g][h4] = acc;
    __syncthreads();
    if (tid < 128) {
        float4 a0 = comb[0][tid], a1 = comb[1][tid], a2 = comb[2][tid], a3 = comb[3][tid];
        float* dst = &g_attended[b * H_ + tid * 4];
        atomicAdd(dst + 0, (a0.x + a1.x) + (a2.x + a3.x));
        atomicAdd(dst + 1, (a0.y + a1.y) + (a2.y + a3.y));
        atomicAdd(dst + 2, (a0.z + a1.z) + (a2.z + a3.z));
        atomicAdd(dst + 3, (a0.w + a1.w) + (a2.w + a3.w));
    }
}

// ---------------- kernel 8: LayerNorm ----------------
__global__ __launch_bounds__(512) void k_ln(const float* __restrict__ gamma,
                                            const float* __restrict__ beta,
                                            float* __restrict__ out) {
    const int b = blockIdx.x;
    const int h = threadIdx.x;
    __shared__ float red[512];
    float x = g_attended[b * H_ + h];
    red[h] = x;
    __syncthreads();
    for (int o = 256; o; o >>= 1) {
        if (h < o) red[h] += red[h + o];
        __syncthreads();
    }
    const float mu = red[0] * (1.f / (float)H_);
    __syncthreads();
    const float d = x - mu;
    red[h] = d * d;
    __syncthreads();
    for (int o = 256; o; o >>= 1) {
        if (h < o) red[h] += red[h + o];
        __syncthreads();
    }
    const float var = red[0] * (1.f / (float)H_);
    out[b * H_ + h] = d * rsqrtf(var + LN_EPS) * gamma[h] + beta[h];
}

extern "C" void kernel_launch(void* const* d_in, const int* in_sizes, int n_in,
                              void* d_out, int out_size) {
    const float* hid = (const float*)d_in[0];
    const float* W = (const float*)d_in[1];
    const float* U = (const float*)d_in[2];
    const float* va = (const float*)d_in[3];
    const float* gamma = (const float*)d_in[4];
    const float* beta = (const float*)d_in[5];
    (void)in_sizes; (void)n_in; (void)out_size;

    float* out = (float*)d_out;
    float* attn = out + B_ * H_;

    cudaFuncSetAttribute(k_gemm, cudaFuncAttributeMaxDynamicSharedMemorySize, SM_TOTAL);

    k_zero<<<128, 256>>>();                            // idx 0
    k_wprep<<<256, 256>>>(W);                          // idx 1
    k_warm<<<512, 256>>>();                            // idx 2
    k_gemm<<<dim3(16, 64), 256, SM_TOTAL>>>(hid, W);   // idx 3 <- ncu capture
    k_uatt<<<B_, 512>>>(U);
    k_scores<<<dim3(16, 64), 256>>>(va);
    k_softmax<<<B_, 256>>>(attn);
    k_attended<<<dim3(16, 64), 512>>>(hid, attn);
    k_ln<<<B_, 512>>>(gamma, beta, out);
}

// round 14
// speedup vs baseline: 1.7695x; 1.7695x over previous
#include <cuda_runtime.h>
#include <cuda_bf16.h>
#include <cuda_fp16.h>
#include <math.h>
#include <stdint.h>

#define B_ 64
#define L_ 2048
#define H_ 512
#define A_ 128
#define LN_EPS 1e-3f
#define KCH 32

#if defined(__CUDA_ARCH__) && defined(__CUDA_ARCH_FEAT_SM103_ALL)
#define HAS_TC 1
#else
#define HAS_TC 0
#endif

// ---------------- device scratch ----------------
__device__ __half g_hatt_h[B_ * L_ * A_];   // 32 MB hatt staging (fp16)
__device__ float g_context[B_ * H_];
__device__ float g_u[B_ * A_];
__device__ float g_scores[B_ * L_];
__device__ float g_attended[B_ * H_];
__device__ __align__(16) unsigned short g_Whi[8 * 8192];
__device__ __align__(16) unsigned short g_Wlo[8 * 8192];

// ---------------- generic helpers ----------------
__device__ __forceinline__ uint32_t smem_u32(const void* p) {
    uint32_t a;
    asm("{ .reg .u64 t; cvta.to.shared.u64 t, %1; cvt.u32.u64 %0, t; }" : "=r"(a) : "l"(p));
    return a;
}
__device__ __forceinline__ unsigned long long pack2(float lo, float hi) {
    unsigned long long r;
    asm("mov.b64 %0, {%1,%2};" : "=l"(r) : "f"(lo), "f"(hi));
    return r;
}
__device__ __forceinline__ void unpack2(unsigned long long v, float& lo, float& hi) {
    asm("mov.b64 {%0,%1}, %2;" : "=f"(lo), "=f"(hi) : "l"(v));
}
#define FMA2(c, a, b) asm("fma.rn.f32x2 %0, %1, %2, %0;" : "+l"(c) : "l"(a), "l"(b))
#define SWZ128(off) ((off) ^ (((off) >> 3) & 0x70))

__device__ __forceinline__ float tanh_hw(float x) {
    float r;
    asm("tanh.approx.f32 %0, %1;" : "=f"(r) : "f"(x));
    return r;
}

#define CP_ASYNC16(dst_smem, src_gptr) \
    asm volatile("cp.async.cg.shared.global [%0], [%1], 16;" \
                 :: "r"((uint32_t)(dst_smem)), "l"(src_gptr) : "memory")
#define CP_ASYNC_COMMIT() asm volatile("cp.async.commit_group;" ::: "memory")
#define CP_ASYNC_WAIT_ALL() asm volatile("cp.async.wait_group 0;" ::: "memory")

// ---------------- tcgen05 helpers ----------------
#define MBARRIER_INIT(addr, cnt) \
    asm volatile("mbarrier.init.shared.b64 [%0], %1;" :: "r"((uint32_t)(addr)), "r"((uint32_t)(cnt)) : "memory")
#define MBARRIER_INVAL(addr) \
    asm volatile("mbarrier.inval.shared.b64 [%0];" :: "r"((uint32_t)(addr)) : "memory")
#define MBARRIER_WAIT_PARITY(mbar_smem_addr, phase_parity) do { \
    uint32_t _mbar = (uint32_t)(mbar_smem_addr); \
    uint32_t _parity = (uint32_t)(phase_parity); \
    uint32_t _done; \
    asm volatile( \
        "{\n\t.reg .pred p;\n\t" \
        "mbarrier.try_wait.parity.acquire.cta.shared::cta.b64 p, [%1], %2;\n\t" \
        "selp.b32 %0, 1, 0, p;\n\t}" \
        : "=r"(_done) : "r"(_mbar), "r"(_parity) : "memory"); \
    if (!_done) { \
        asm volatile( \
            "{\n\t.reg .pred P1;\n\t" \
            "WAIT_LOOP_%=:\n\t" \
            "mbarrier.try_wait.parity.acquire.cta.shared::cta.b64 P1, [%0], %1, 0x989680;\n\t" \
            "@P1 bra.uni WAIT_DONE_%=;\n\t" \
            "bra.uni WAIT_LOOP_%=;\n\t" \
            "WAIT_DONE_%=:\n\t}" \
            :: "r"(_mbar), "r"(_parity) : "memory"); \
    } \
} while(0)
#define TCGEN05_ALLOC(smem_res, nCols) \
    asm volatile("tcgen05.alloc.cta_group::1.sync.aligned.shared::cta.b32 [%0], %1;" \
                 :: "r"((uint32_t)(smem_res)), "r"((uint32_t)(nCols)) : "memory")
#define TCGEN05_DEALLOC(tmem, nCols) \
    asm volatile("tcgen05.dealloc.cta_group::1.sync.aligned.b32 %0, %1;" :: "r"(tmem), "r"((uint32_t)(nCols)))
#define TCGEN05_RELINQ() \
    asm volatile("tcgen05.relinquish_alloc_permit.cta_group::1.sync.aligned;")
#define TCGEN05_COMMIT(mbar) \
    asm volatile("tcgen05.commit.cta_group::1.mbarrier::arrive::one.shared::cluster.b64 [%0];" \
                 :: "r"((uint32_t)(mbar)) : "memory")
#define TCGEN05_WAIT_LD() asm volatile("tcgen05.wait::ld.sync.aligned;" ::: "memory")
#define TCGEN05_FENCE_AFTER() asm volatile("tcgen05.fence::after_thread_sync;" ::: "memory")
#define TCGEN05_FENCE_BEFORE() asm volatile("tcgen05.fence::before_thread_sync;" ::: "memory")
#define FENCE_PROXY_ASYNC() asm volatile("fence.proxy.async.shared::cta;" ::: "memory")
#define TCGEN05_LD_32X32B_X32(r, tmem_addr) \
    asm volatile( \
        "tcgen05.ld.sync.aligned.32x32b.x32.b32 " \
        "{%0, %1, %2, %3, %4, %5, %6, %7, " \
        " %8, %9, %10, %11, %12, %13, %14, %15, " \
        " %16, %17, %18, %19, %20, %21, %22, %23, " \
        " %24, %25, %26, %27, %28, %29, %30, %31}, [%32];" \
        : "=r"((r)[0]),  "=r"((r)[1]),  "=r"((r)[2]),  "=r"((r)[3]), \
          "=r"((r)[4]),  "=r"((r)[5]),  "=r"((r)[6]),  "=r"((r)[7]), \
          "=r"((r)[8]),  "=r"((r)[9]),  "=r"((r)[10]), "=r"((r)[11]), \
          "=r"((r)[12]), "=r"((r)[13]), "=r"((r)[14]), "=r"((r)[15]), \
          "=r"((r)[16]), "=r"((r)[17]), "=r"((r)[18]), "=r"((r)[19]), \
          "=r"((r)[20]), "=r"((r)[21]), "=r"((r)[22]), "=r"((r)[23]), \
          "=r"((r)[24]), "=r"((r)[25]), "=r"((r)[26]), "=r"((r)[27]), \
          "=r"((r)[28]), "=r"((r)[29]), "=r"((r)[30]), "=r"((r)[31]) \
        : "r"(tmem_addr))

static constexpr uint64_t SMEM_DESC_BASE_SW128 =
    (uint64_t(2) << 61) | (uint64_t(1) << 46) | (uint64_t(64) << 32) | (uint64_t(1) << 16);
#define MAKE_SMEM_DESC(base) (SMEM_DESC_BASE_SW128 | ((uint64_t)((base) >> 4) & 0x3FFF))
#define IDESC_BF16_M128_N128 0x8200490u

#if HAS_TC
__device__ __forceinline__ void mma_f16_ss_cg1(uint32_t d_tmem, uint64_t a_desc,
                                               uint64_t b_desc, uint32_t idesc, uint32_t en) {
    asm volatile(
        "{\n\t.reg .pred p;\n\t"
        "setp.ne.u32 p, %4, 0;\n\t"
        "tcgen05.mma.cta_group::1.kind::f16 [%0], %1, %2, %3, {%5, %5, %5, %5}, p;\n\t}"
        :: "r"(d_tmem), "l"(a_desc), "l"(b_desc), "r"(idesc), "r"(en), "r"(0u)
        : "memory");
}
#endif

// ---------------- smem layout (R11 config: 66560 B -> 3 CTAs/SM) ----------------
#define SM_TMEM 0
#define SM_MBAR 8
#define SM_CTX  64
#define SM_AHI  1024
#define SM_ALO  (1024 + 16384)
#define SM_WHI  (1024 + 2 * 16384)
#define SM_WLO  (1024 + 3 * 16384)
#define SM_TOTAL (1024 + 4 * 16384)

// ---------------- kernel: prep (fused zero + wprep) ----------------
__global__ void k_prep(const float* __restrict__ W) {
    int i = blockIdx.x * blockDim.x + threadIdx.x;  // 0..65535
    if (i < B_ * H_) {
        g_context[i] = 0.f;
        g_attended[i] = 0.f;
    }
    int c = i >> 13;
    int rem = i & 8191;
    int n = rem >> 6;
    int kk = rem & 63;
    float x = W[(size_t)(c * 64 + kk) * A_ + n];
    __nv_bfloat16 hi = __float2bfloat16(x);
    float hif = __bfloat162float(hi);
    __nv_bfloat16 lo = __float2bfloat16(x - hif);
    uint32_t off = n * 128 + kk * 2;
    uint32_t sw = SWZ128(off);
    g_Whi[c * 8192 + (sw >> 1)] = __bfloat16_as_ushort(hi);
    g_Wlo[c * 8192 + (sw >> 1)] = __bfloat16_as_ushort(lo);
}

// ---------------- kernel 1: GEMM hatt = hidden @ W (R11 structure, fp16 epilogue) ----------------
__global__ __launch_bounds__(256) void k_gemm(const float* __restrict__ hid,
                                              const float* __restrict__ W) {
    extern __shared__ char smem[];
#if HAS_TC
    const uint32_t smem_base = smem_u32(smem);
    const int tid = threadIdx.x;
    const int wid = tid >> 5;
    const int lid = tid & 31;
    const int b = blockIdx.y;
    const int l0 = blockIdx.x * 128;

    float* ctxs = (float*)(smem + SM_CTX);

    if (wid == 0) {
        TCGEN05_ALLOC(smem_base + SM_TMEM, 128);
        TCGEN05_RELINQ();
    }
    if (tid == 0) MBARRIER_INIT(smem_base + SM_MBAR, 1);
    if (tid < 64) ctxs[tid] = 0.f;
    __syncthreads();

    uint32_t tmem_base;
    asm volatile("ld.shared.b32 %0, [%1];" : "=r"(tmem_base) : "r"(smem_base + SM_TMEM));

    const float* Ab0 = hid + ((size_t)b * L_ + l0) * H_;
    const uint64_t ah_desc = MAKE_SMEM_DESC(smem_base + SM_AHI);
    const uint64_t al_desc = MAKE_SMEM_DESC(smem_base + SM_ALO);
    const uint64_t wh_desc = MAKE_SMEM_DESC(smem_base + SM_WHI);
    const uint64_t wl_desc = MAKE_SMEM_DESC(smem_base + SM_WLO);

    const int kk2 = tid & 31;
    const int rbase = tid >> 5;
    const float* Arow = Ab0 + kk2 * 2;

    float2 areg[16];
#pragma unroll
    for (int i = 0; i < 16; i++)
        areg[i] = *(const float2*)(Arow + (size_t)(i * 8 + rbase) * H_);

    for (int kc = 0; kc < 8; kc++) {
        const int k0 = kc * 64;

        // W tiles via cp.async (latency hides under convert)
        {
            const char* wh = (const char*)(g_Whi + (size_t)kc * 8192);
            const char* wl = (const char*)(g_Wlo + (size_t)kc * 8192);
#pragma unroll
            for (int p = 0; p < 4; p++) {
                const uint32_t o = (uint32_t)(p * 256 + tid) * 16;
                CP_ASYNC16(smem_base + SM_WHI + o, wh + o);
                CP_ASYNC16(smem_base + SM_WLO + o, wl + o);
            }
            CP_ASYNC_COMMIT();
        }

        // convert prefetched A (chunk kc); fold column sums
        float csum0 = 0.f, csum1 = 0.f;
#pragma unroll
        for (int i = 0; i < 16; i++) {
            const int r = i * 8 + rbase;
            const float2 v = areg[i];
            csum0 += v.x;
            csum1 += v.y;
            uint32_t hi2, lo2;
            asm("cvt.rn.bf16x2.f32 %0, %1, %2;" : "=r"(hi2) : "f"(v.y), "f"(v.x));
            const float hif0 = __uint_as_float(hi2 << 16);
            const float hif1 = __uint_as_float(hi2 & 0xffff0000u);
            asm("cvt.rn.bf16x2.f32 %0, %1, %2;" : "=r"(lo2) : "f"(v.y - hif1), "f"(v.x - hif0));
            const uint32_t sw = SWZ128((uint32_t)r * 128 + (uint32_t)kk2 * 4);
            *(uint32_t*)(smem + SM_AHI + sw) = hi2;
            *(uint32_t*)(smem + SM_ALO + sw) = lo2;
        }
        atomicAdd(&ctxs[kk2 * 2], csum0);
        atomicAdd(&ctxs[kk2 * 2 + 1], csum1);

        // prefetch A chunk kc+1
        if (kc < 7) {
            const float* Anext = Arow + (kc + 1) * 64;
#pragma unroll
            for (int i = 0; i < 16; i++)
                areg[i] = *(const float2*)(Anext + (size_t)(i * 8 + rbase) * H_);
        }

        CP_ASYNC_WAIT_ALL();
        FENCE_PROXY_ASYNC();
        __syncthreads();

        if (wid == 0) {
            uint32_t one;
            asm volatile("{\n\t.reg .pred p;\n\telect.sync _|p, 0xFFFFFFFF;\n\tselp.b32 %0, 1, 0, p;\n\t}" : "=r"(one));
            if (one) {
#pragma unroll
                for (int s = 0; s < 4; s++) {
                    const uint64_t ds = (uint64_t)(2 * s);
                    mma_f16_ss_cg1(tmem_base, ah_desc + ds, wh_desc + ds, IDESC_BF16_M128_N128,
                                   (kc == 0 && s == 0) ? 0u : 1u);
                    mma_f16_ss_cg1(tmem_base, ah_desc + ds, wl_desc + ds, IDESC_BF16_M128_N128, 1u);
                    mma_f16_ss_cg1(tmem_base, al_desc + ds, wh_desc + ds, IDESC_BF16_M128_N128, 1u);
                }
                TCGEN05_COMMIT(smem_base + SM_MBAR);
            }
        }

        if (tid < 64) {
            float v = ctxs[tid];
            ctxs[tid] = 0.f;
            atomicAdd(&g_context[b * H_ + k0 + tid], v);
        }
        MBARRIER_WAIT_PARITY(smem_base + SM_MBAR, kc & 1);
        __syncthreads();
    }

    TCGEN05_FENCE_AFTER();

    // epilogue: TMEM -> padded smem slab -> fp16 half2-packed coalesced gmem
    float* slab = (float*)(smem + SM_AHI);
    uint32_t* Cb = (uint32_t*)(g_hatt_h + ((size_t)b * L_ + l0) * A_);
    for (int cb = 0; cb < 4; cb++) {
        if (wid < 4) {
            uint32_t r[32];
            TCGEN05_LD_32X32B_X32(r, tmem_base + cb * 32);
            TCGEN05_WAIT_LD();
            const int row = wid * 32 + lid;
#pragma unroll
            for (int j = 0; j < 32; j++) slab[row * 33 + j] = __uint_as_float(r[j]);
        }
        __syncthreads();
#pragma unroll
        for (int it = 0; it < 8; it++) {
            const int idx = it * 256 + tid;
            const int row = idx >> 4;
            const int c2 = idx & 15;
            __half2 h = __floats2half2_rn(slab[row * 33 + c2 * 2], slab[row * 33 + c2 * 2 + 1]);
            Cb[(size_t)row * (A_ / 2) + cb * 16 + c2] = *(uint32_t*)&h;
        }
        __syncthreads();
    }

    TCGEN05_FENCE_BEFORE();
    if (tid == 0) MBARRIER_INVAL(smem_base + SM_MBAR);
    __syncthreads();
    if (wid == 0) TCGEN05_DEALLOC(tmem_base, 128);

#else  // ---------------- FFMA2 fallback ----------------
    float* As = (float*)smem;
    float* Bs = As + KCH * 128;

    const int tile = blockIdx.x;
    const int b = blockIdx.y;
    const int l0 = tile * 128;
    const int tid = threadIdx.x;
    const int tx = tid & 15, ty = tid >> 4;
    const int c0 = tx * 8, r0 = ty * 8;

    unsigned long long acc[8][4];
#pragma unroll
    for (int i = 0; i < 8; i++)
#pragma unroll
        for (int j = 0; j < 4; j++) acc[i][j] = 0ULL;

    const float* Abase = hid + ((size_t)(b * L_ + l0)) * H_;

    for (int kc = 0; kc < H_ / KCH; kc++) {
        const int k0 = kc * KCH;
#pragma unroll
        for (int p = 0; p < 4; p++) {
            int f4 = p * 256 + tid;
            int row = f4 >> 3;
            int kq = f4 & 7;
            float4 v = *(const float4*)(Abase + (size_t)row * H_ + k0 + kq * 4);
            As[(kq * 4 + 0) * 128 + row] = v.x;
            As[(kq * 4 + 1) * 128 + row] = v.y;
            As[(kq * 4 + 2) * 128 + row] = v.z;
            As[(kq * 4 + 3) * 128 + row] = v.w;
        }
#pragma unroll
        for (int p = 0; p < 4; p++) {
            int f4 = p * 256 + tid;
            int kk = f4 >> 5;
            int c4 = f4 & 31;
            *(float4*)&Bs[kk * 128 + c4 * 4] = *(const float4*)(W + (size_t)(k0 + kk) * A_ + c4 * 4);
        }
        __syncthreads();

        if (tid < 32) {
            float s = 0.f;
#pragma unroll 8
            for (int r = 0; r < 128; r++) s += As[tid * 128 + ((r + tid) & 127)];
            atomicAdd(&g_context[b * H_ + k0 + tid], s);
        }

#pragma unroll 8
        for (int kk = 0; kk < KCH; kk++) {
            float4 a0 = *(const float4*)&As[kk * 128 + r0];
            float4 a1 = *(const float4*)&As[kk * 128 + r0 + 4];
            ulonglong2 b01 = *(const ulonglong2*)&Bs[kk * 128 + c0];
            ulonglong2 b23 = *(const ulonglong2*)&Bs[kk * 128 + c0 + 4];
            unsigned long long bb0 = b01.x, bb1 = b01.y, bb2 = b23.x, bb3 = b23.y;
            float av[8] = {a0.x, a0.y, a0.z, a0.w, a1.x, a1.y, a1.z, a1.w};
#pragma unroll
            for (int i = 0; i < 8; i++) {
                unsigned long long ap = pack2(av[i], av[i]);
                FMA2(acc[i][0], ap, bb0);
                FMA2(acc[i][1], ap, bb1);
                FMA2(acc[i][2], ap, bb2);
                FMA2(acc[i][3], ap, bb3);
            }
        }
        __syncthreads();
    }

    __half* Cbase = g_hatt_h + ((size_t)(b * L_ + l0 + r0)) * A_ + c0;
#pragma unroll
    for (int i = 0; i < 8; i++) {
        float o[8];
#pragma unroll
        for (int j = 0; j < 4; j++) unpack2(acc[i][j], o[2 * j], o[2 * j + 1]);
#pragma unroll
        for (int j = 0; j < 8; j++) Cbase[(size_t)i * A_ + j] = __float2half_rn(o[j]);
    }
#endif
}

// ---------------- kernel 2: u[b][a] = (mean context) @ U_a ----------------
__global__ __launch_bounds__(512) void k_uatt(const float* __restrict__ U) {
    const int b = blockIdx.x;
    const int tid = threadIdx.x;
    const int a = tid & 127;
    const int q = tid >> 7;
    __shared__ float c[H_];
    __shared__ float part[4][128];
    c[tid] = g_context[b * H_ + tid] * (1.f / (float)L_);
    __syncthreads();
    const float* Up = U + (size_t)(q * 128) * A_ + a;
    const float* cp = c + q * 128;
    float s0 = 0.f, s1 = 0.f, s2 = 0.f, s3 = 0.f;
#pragma unroll 8
    for (int hh = 0; hh < 128; hh += 4) {
        s0 += cp[hh] * Up[(size_t)hh * A_];
        s1 += cp[hh + 1] * Up[(size_t)(hh + 1) * A_];
        s2 += cp[hh + 2] * Up[(size_t)(hh + 2) * A_];
        s3 += cp[hh + 3] * Up[(size_t)(hh + 3) * A_];
    }
    part[q][a] = (s0 + s1) + (s2 + s3);
    __syncthreads();
    if (tid < 128) {
        g_u[b * A_ + tid] = (part[0][tid] + part[1][tid]) + (part[2][tid] + part[3][tid]);
    }
}

// ---------------- kernel 3: scores = v^T tanh_hw(hatt_fp16 + u), MLP=16 ----------------
__global__ __launch_bounds__(256) void k_scores(const float* __restrict__ va) {
    __shared__ float su[A_], sv[A_];
    const int tile = blockIdx.x, b = blockIdx.y;
    const int tid = threadIdx.x;
    if (tid < A_) {
        su[tid] = g_u[b * A_ + tid];
        sv[tid] = va[tid];
    }
    __syncthreads();
    const int w = tid >> 5, lane = tid & 31;
    const float4 u4 = *(const float4*)&su[lane * 4];
    const float4 v4 = *(const float4*)&sv[lane * 4];

    uint2 hraw[16];
    const uint32_t* base =
        (const uint32_t*)(g_hatt_h + ((size_t)(b * L_ + tile * 128 + w * 16)) * A_) + lane * 2;
#pragma unroll
    for (int t = 0; t < 16; t++)
        hraw[t] = *(const uint2*)(base + (size_t)t * (A_ / 2));

#pragma unroll
    for (int t = 0; t < 16; t++) {
        const float2 h01 = __half22float2(*(const __half2*)&hraw[t].x);
        const float2 h23 = __half22float2(*(const __half2*)&hraw[t].y);
        float s = v4.x * tanh_hw(h01.x + u4.x) + v4.y * tanh_hw(h01.y + u4.y) +
                  v4.z * tanh_hw(h23.x + u4.z) + v4.w * tanh_hw(h23.y + u4.w);
#pragma unroll
        for (int o = 16; o; o >>= 1) s += __shfl_down_sync(0xffffffffu, s, o);
        if (lane == 0) g_scores[b * L_ + tile * 128 + w * 16 + t] = s;
    }
}

// ---------------- kernel 4: softmax over L, write attn to d_out ----------------
__global__ void k_softmax(float* __restrict__ attn_out) {
    const int b = blockIdx.x;
    const int tid = threadIdx.x;
    __shared__ float red[256];
    float vals[8];
    float m = -1e30f;
#pragma unroll
    for (int i = 0; i < 8; i++) {
        vals[i] = g_scores[b * L_ + tid + 256 * i];
        m = fmaxf(m, vals[i]);
    }
    red[tid] = m;
    __syncthreads();
    for (int o = 128; o; o >>= 1) {
        if (tid < o) red[tid] = fmaxf(red[tid], red[tid + o]);
        __syncthreads();
    }
    m = red[0];
    __syncthreads();
    float sum = 0.f;
#pragma unroll
    for (int i = 0; i < 8; i++) {
        vals[i] = __expf(vals[i] - m);
        sum += vals[i];
    }
    red[tid] = sum;
    __syncthreads();
    for (int o = 128; o; o >>= 1) {
        if (tid < o) red[tid] += red[tid + o];
        __syncthreads();
    }
    const float inv = 1.f / red[0];
#pragma unroll
    for (int i = 0; i < 8; i++) attn_out[b * L_ + tid + 256 * i] = vals[i] * inv;
}

// ---------------- kernel 5: attended ----------------
__global__ __launch_bounds__(512) void k_attended(const float* __restrict__ hid,
                                                  const float* __restrict__ attn) {
    const int tile = blockIdx.x, b = blockIdx.y;
    const int tid = threadIdx.x;
    const int g = tid >> 7;
    const int h4 = tid & 127;
    __shared__ float sa[128];
    __shared__ float4 comb[4][128];
    if (tid < 128) sa[tid] = attn[b * L_ + tile * 128 + tid];
    __syncthreads();
    const float4* hp = (const float4*)(hid + ((size_t)(b * L_) + tile * 128 + g * 32) * H_) + h4;
    const float* sap = sa + g * 32;
    float4 acc = {0.f, 0.f, 0.f, 0.f};
#pragma unroll 4
    for (int l = 0; l < 32; l++) {
        const float w = sap[l];
        const float4 v = hp[(size_t)l * (H_ / 4)];
        acc.x += w * v.x;
        acc.y += w * v.y;
        acc.z += w * v.z;
        acc.w += w * v.w;
    }
    comb[g][h4] = acc;
    __syncthreads();
    if (tid < 128) {
        float4 a0 = comb[0][tid], a1 = comb[1][tid], a2 = comb[2][tid], a3 = comb[3][tid];
        float* dst = &g_attended[b * H_ + tid * 4];
        atomicAdd(dst + 0, (a0.x + a1.x) + (a2.x + a3.x));
        atomicAdd(dst + 1, (a0.y + a1.y) + (a2.y + a3.y));
        atomicAdd(dst + 2, (a0.z + a1.z) + (a2.z + a3.z));
        atomicAdd(dst + 3, (a0.w + a1.w) + (a2.w + a3.w));
    }
}

// ---------------- kernel 6: LayerNorm ----------------
__global__ __launch_bounds__(512) void k_ln(const float* __restrict__ gamma,
                                            const float* __restrict__ beta,
                                            float* __restrict__ out) {
    const int b = blockIdx.x;
    const int h = threadIdx.x;
    __shared__ float red[512];
    float x = g_attended[b * H_ + h];
    red[h] = x;
    __syncthreads();
    for (int o = 256; o; o >>= 1) {
        if (h < o) red[h] += red[h + o];
        __syncthreads();
    }
    const float mu = red[0] * (1.f / (float)H_);
    __syncthreads();
    const float d = x - mu;
    red[h] = d * d;
    __syncthreads();
    for (int o = 256; o; o >>= 1) {
        if (h < o) red[h] += red[h + o];
        __syncthreads();
    }
    const float var = red[0] * (1.f / (float)H_);
    out[b * H_ + h] = d * rsqrtf(var + LN_EPS) * gamma[h] + beta[h];
}

extern "C" void kernel_launch(void* const* d_in, const int* in_sizes, int n_in,
                              void* d_out, int out_size) {
    const float* hid = (const float*)d_in[0];
    const float* W = (const float*)d_in[1];
    const float* U = (const float*)d_in[2];
    const float* va = (const float*)d_in[3];
    const float* gamma = (const float*)d_in[4];
    const float* beta = (const float*)d_in[5];
    (void)in_sizes; (void)n_in; (void)out_size;

    float* out = (float*)d_out;
    float* attn = out + B_ * H_;

    cudaFuncSetAttribute(k_gemm, cudaFuncAttributeMaxDynamicSharedMemorySize, SM_TOTAL);

    k_prep<<<256, 256>>>(W);
    k_gemm<<<dim3(16, 64), 256, SM_TOTAL>>>(hid, W);
    k_uatt<<<B_, 512>>>(U);
    k_scores<<<dim3(16, 64), 256>>>(va);
    k_softmax<<<B_, 256>>>(attn);
    k_attended<<<dim3(16, 64), 512>>>(hid, attn);
    k_ln<<<B_, 512>>>(gamma, beta, out);
}

// round 15
// speedup vs baseline: 1.7764x; 1.0039x over previous
#include <cuda_runtime.h>
#include <cuda_bf16.h>
#include <cuda_fp16.h>
#include <math.h>
#include <stdint.h>

#define B_ 64
#define L_ 2048
#define H_ 512
#define A_ 128
#define LN_EPS 1e-3f
#define KCH 32

#if defined(__CUDA_ARCH__) && defined(__CUDA_ARCH_FEAT_SM103_ALL)
#define HAS_TC 1
#else
#define HAS_TC 0
#endif

// ---------------- device scratch ----------------
__device__ __half g_hatt_h[B_ * L_ * A_];   // 32 MB hatt staging (fp16)
__device__ float g_context[B_ * H_];
__device__ float g_u[B_ * A_];
__device__ float g_scores[B_ * L_];
__device__ float g_attended[B_ * H_];
__device__ __align__(16) unsigned short g_Whi[8 * 8192];
__device__ __align__(16) unsigned short g_Wlo[8 * 8192];

// ---------------- generic helpers ----------------
__device__ __forceinline__ uint32_t smem_u32(const void* p) {
    uint32_t a;
    asm("{ .reg .u64 t; cvta.to.shared.u64 t, %1; cvt.u32.u64 %0, t; }" : "=r"(a) : "l"(p));
    return a;
}
__device__ __forceinline__ unsigned long long pack2(float lo, float hi) {
    unsigned long long r;
    asm("mov.b64 %0, {%1,%2};" : "=l"(r) : "f"(lo), "f"(hi));
    return r;
}
__device__ __forceinline__ void unpack2(unsigned long long v, float& lo, float& hi) {
    asm("mov.b64 {%0,%1}, %2;" : "=f"(lo), "=f"(hi) : "l"(v));
}
#define FMA2(c, a, b) asm("fma.rn.f32x2 %0, %1, %2, %0;" : "+l"(c) : "l"(a), "l"(b))
#define SWZ128(off) ((off) ^ (((off) >> 3) & 0x70))

__device__ __forceinline__ float tanh_hw(float x) {
    float r;
    asm("tanh.approx.f32 %0, %1;" : "=f"(r) : "f"(x));
    return r;
}

#define CP_ASYNC16(dst_smem, src_gptr) \
    asm volatile("cp.async.cg.shared.global [%0], [%1], 16;" \
                 :: "r"((uint32_t)(dst_smem)), "l"(src_gptr) : "memory")
#define CP_ASYNC_COMMIT() asm volatile("cp.async.commit_group;" ::: "memory")
#define CP_ASYNC_WAIT_ALL() asm volatile("cp.async.wait_group 0;" ::: "memory")

// ---------------- tcgen05 helpers ----------------
#define MBARRIER_INIT(addr, cnt) \
    asm volatile("mbarrier.init.shared.b64 [%0], %1;" :: "r"((uint32_t)(addr)), "r"((uint32_t)(cnt)) : "memory")
#define MBARRIER_INVAL(addr) \
    asm volatile("mbarrier.inval.shared.b64 [%0];" :: "r"((uint32_t)(addr)) : "memory")
#define MBARRIER_WAIT_PARITY(mbar_smem_addr, phase_parity) do { \
    uint32_t _mbar = (uint32_t)(mbar_smem_addr); \
    uint32_t _parity = (uint32_t)(phase_parity); \
    uint32_t _done; \
    asm volatile( \
        "{\n\t.reg .pred p;\n\t" \
        "mbarrier.try_wait.parity.acquire.cta.shared::cta.b64 p, [%1], %2;\n\t" \
        "selp.b32 %0, 1, 0, p;\n\t}" \
        : "=r"(_done) : "r"(_mbar), "r"(_parity) : "memory"); \
    if (!_done) { \
        asm volatile( \
            "{\n\t.reg .pred P1;\n\t" \
            "WAIT_LOOP_%=:\n\t" \
            "mbarrier.try_wait.parity.acquire.cta.shared::cta.b64 P1, [%0], %1, 0x989680;\n\t" \
            "@P1 bra.uni WAIT_DONE_%=;\n\t" \
            "bra.uni WAIT_LOOP_%=;\n\t" \
            "WAIT_DONE_%=:\n\t}" \
            :: "r"(_mbar), "r"(_parity) : "memory"); \
    } \
} while(0)
#define TCGEN05_ALLOC(smem_res, nCols) \
    asm volatile("tcgen05.alloc.cta_group::1.sync.aligned.shared::cta.b32 [%0], %1;" \
                 :: "r"((uint32_t)(smem_res)), "r"((uint32_t)(nCols)) : "memory")
#define TCGEN05_DEALLOC(tmem, nCols) \
    asm volatile("tcgen05.dealloc.cta_group::1.sync.aligned.b32 %0, %1;" :: "r"(tmem), "r"((uint32_t)(nCols)))
#define TCGEN05_RELINQ() \
    asm volatile("tcgen05.relinquish_alloc_permit.cta_group::1.sync.aligned;")
#define TCGEN05_COMMIT(mbar) \
    asm volatile("tcgen05.commit.cta_group::1.mbarrier::arrive::one.shared::cluster.b64 [%0];" \
                 :: "r"((uint32_t)(mbar)) : "memory")
#define TCGEN05_WAIT_LD() asm volatile("tcgen05.wait::ld.sync.aligned;" ::: "memory")
#define TCGEN05_FENCE_AFTER() asm volatile("tcgen05.fence::after_thread_sync;" ::: "memory")
#define TCGEN05_FENCE_BEFORE() asm volatile("tcgen05.fence::before_thread_sync;" ::: "memory")
#define FENCE_PROXY_ASYNC() asm volatile("fence.proxy.async.shared::cta;" ::: "memory")
#define TCGEN05_LD_32X32B_X32(r, tmem_addr) \
    asm volatile( \
        "tcgen05.ld.sync.aligned.32x32b.x32.b32 " \
        "{%0, %1, %2, %3, %4, %5, %6, %7, " \
        " %8, %9, %10, %11, %12, %13, %14, %15, " \
        " %16, %17, %18, %19, %20, %21, %22, %23, " \
        " %24, %25, %26, %27, %28, %29, %30, %31}, [%32];" \
        : "=r"((r)[0]),  "=r"((r)[1]),  "=r"((r)[2]),  "=r"((r)[3]), \
          "=r"((r)[4]),  "=r"((r)[5]),  "=r"((r)[6]),  "=r"((r)[7]), \
          "=r"((r)[8]),  "=r"((r)[9]),  "=r"((r)[10]), "=r"((r)[11]), \
          "=r"((r)[12]), "=r"((r)[13]), "=r"((r)[14]), "=r"((r)[15]), \
          "=r"((r)[16]), "=r"((r)[17]), "=r"((r)[18]), "=r"((r)[19]), \
          "=r"((r)[20]), "=r"((r)[21]), "=r"((r)[22]), "=r"((r)[23]), \
          "=r"((r)[24]), "=r"((r)[25]), "=r"((r)[26]), "=r"((r)[27]), \
          "=r"((r)[28]), "=r"((r)[29]), "=r"((r)[30]), "=r"((r)[31]) \
        : "r"(tmem_addr))

static constexpr uint64_t SMEM_DESC_BASE_SW128 =
    (uint64_t(2) << 61) | (uint64_t(1) << 46) | (uint64_t(64) << 32) | (uint64_t(1) << 16);
#define MAKE_SMEM_DESC(base) (SMEM_DESC_BASE_SW128 | ((uint64_t)((base) >> 4) & 0x3FFF))
#define IDESC_BF16_M128_N128 0x8200490u

#if HAS_TC
__device__ __forceinline__ void mma_f16_ss_cg1(uint32_t d_tmem, uint64_t a_desc,
                                               uint64_t b_desc, uint32_t idesc, uint32_t en) {
    asm volatile(
        "{\n\t.reg .pred p;\n\t"
        "setp.ne.u32 p, %4, 0;\n\t"
        "tcgen05.mma.cta_group::1.kind::f16 [%0], %1, %2, %3, {%5, %5, %5, %5}, p;\n\t}"
        :: "r"(d_tmem), "l"(a_desc), "l"(b_desc), "r"(idesc), "r"(en), "r"(0u)
        : "memory");
}
#endif

// ---------------- smem layout (R11 config: 66560 B -> 3 CTAs/SM) ----------------
#define SM_TMEM 0
#define SM_MBAR 8
#define SM_CTX  64
#define SM_AHI  1024
#define SM_ALO  (1024 + 16384)
#define SM_WHI  (1024 + 2 * 16384)
#define SM_WLO  (1024 + 3 * 16384)
#define SM_TOTAL (1024 + 4 * 16384)

// ---------------- kernel: prep (fused zero + wprep) ----------------
__global__ void k_prep(const float* __restrict__ W) {
    int i = blockIdx.x * blockDim.x + threadIdx.x;  // 0..65535
    if (i < B_ * H_) {
        g_context[i] = 0.f;
        g_attended[i] = 0.f;
    }
    int c = i >> 13;
    int rem = i & 8191;
    int n = rem >> 6;
    int kk = rem & 63;
    float x = W[(size_t)(c * 64 + kk) * A_ + n];
    __nv_bfloat16 hi = __float2bfloat16(x);
    float hif = __bfloat162float(hi);
    __nv_bfloat16 lo = __float2bfloat16(x - hif);
    uint32_t off = n * 128 + kk * 2;
    uint32_t sw = SWZ128(off);
    g_Whi[c * 8192 + (sw >> 1)] = __bfloat16_as_ushort(hi);
    g_Wlo[c * 8192 + (sw >> 1)] = __bfloat16_as_ushort(lo);
}

// ---------------- kernel 1: GEMM hatt = hidden @ W (R11 structure, fp16 epilogue) ----------------
__global__ __launch_bounds__(256) void k_gemm(const float* __restrict__ hid,
                                              const float* __restrict__ W) {
    extern __shared__ char smem[];
#if HAS_TC
    const uint32_t smem_base = smem_u32(smem);
    const int tid = threadIdx.x;
    const int wid = tid >> 5;
    const int lid = tid & 31;
    const int b = blockIdx.y;
    const int l0 = blockIdx.x * 128;

    float* ctxs = (float*)(smem + SM_CTX);

    if (wid == 0) {
        TCGEN05_ALLOC(smem_base + SM_TMEM, 128);
        TCGEN05_RELINQ();
    }
    if (tid == 0) MBARRIER_INIT(smem_base + SM_MBAR, 1);
    if (tid < 64) ctxs[tid] = 0.f;
    __syncthreads();

    uint32_t tmem_base;
    asm volatile("ld.shared.b32 %0, [%1];" : "=r"(tmem_base) : "r"(smem_base + SM_TMEM));

    const float* Ab0 = hid + ((size_t)b * L_ + l0) * H_;
    const uint64_t ah_desc = MAKE_SMEM_DESC(smem_base + SM_AHI);
    const uint64_t al_desc = MAKE_SMEM_DESC(smem_base + SM_ALO);
    const uint64_t wh_desc = MAKE_SMEM_DESC(smem_base + SM_WHI);
    const uint64_t wl_desc = MAKE_SMEM_DESC(smem_base + SM_WLO);

    const int kk2 = tid & 31;
    const int rbase = tid >> 5;
    const float* Arow = Ab0 + kk2 * 2;

    float2 areg[16];
#pragma unroll
    for (int i = 0; i < 16; i++)
        areg[i] = *(const float2*)(Arow + (size_t)(i * 8 + rbase) * H_);

    for (int kc = 0; kc < 8; kc++) {
        const int k0 = kc * 64;

        // W tiles via cp.async (latency hides under convert)
        {
            const char* wh = (const char*)(g_Whi + (size_t)kc * 8192);
            const char* wl = (const char*)(g_Wlo + (size_t)kc * 8192);
#pragma unroll
            for (int p = 0; p < 4; p++) {
                const uint32_t o = (uint32_t)(p * 256 + tid) * 16;
                CP_ASYNC16(smem_base + SM_WHI + o, wh + o);
                CP_ASYNC16(smem_base + SM_WLO + o, wl + o);
            }
            CP_ASYNC_COMMIT();
        }

        // convert prefetched A (chunk kc); fold column sums
        float csum0 = 0.f, csum1 = 0.f;
#pragma unroll
        for (int i = 0; i < 16; i++) {
            const int r = i * 8 + rbase;
            const float2 v = areg[i];
            csum0 += v.x;
            csum1 += v.y;
            uint32_t hi2, lo2;
            asm("cvt.rn.bf16x2.f32 %0, %1, %2;" : "=r"(hi2) : "f"(v.y), "f"(v.x));
            const float hif0 = __uint_as_float(hi2 << 16);
            const float hif1 = __uint_as_float(hi2 & 0xffff0000u);
            asm("cvt.rn.bf16x2.f32 %0, %1, %2;" : "=r"(lo2) : "f"(v.y - hif1), "f"(v.x - hif0));
            const uint32_t sw = SWZ128((uint32_t)r * 128 + (uint32_t)kk2 * 4);
            *(uint32_t*)(smem + SM_AHI + sw) = hi2;
            *(uint32_t*)(smem + SM_ALO + sw) = lo2;
        }
        atomicAdd(&ctxs[kk2 * 2], csum0);
        atomicAdd(&ctxs[kk2 * 2 + 1], csum1);

        // prefetch A chunk kc+1
        if (kc < 7) {
            const float* Anext = Arow + (kc + 1) * 64;
#pragma unroll
            for (int i = 0; i < 16; i++)
                areg[i] = *(const float2*)(Anext + (size_t)(i * 8 + rbase) * H_);
        }

        CP_ASYNC_WAIT_ALL();
        FENCE_PROXY_ASYNC();
        __syncthreads();

        if (wid == 0) {
            uint32_t one;
            asm volatile("{\n\t.reg .pred p;\n\telect.sync _|p, 0xFFFFFFFF;\n\tselp.b32 %0, 1, 0, p;\n\t}" : "=r"(one));
            if (one) {
#pragma unroll
                for (int s = 0; s < 4; s++) {
                    const uint64_t ds = (uint64_t)(2 * s);
                    mma_f16_ss_cg1(tmem_base, ah_desc + ds, wh_desc + ds, IDESC_BF16_M128_N128,
                                   (kc == 0 && s == 0) ? 0u : 1u);
                    mma_f16_ss_cg1(tmem_base, ah_desc + ds, wl_desc + ds, IDESC_BF16_M128_N128, 1u);
                    mma_f16_ss_cg1(tmem_base, al_desc + ds, wh_desc + ds, IDESC_BF16_M128_N128, 1u);
                }
                TCGEN05_COMMIT(smem_base + SM_MBAR);
            }
        }

        if (tid < 64) {
            float v = ctxs[tid];
            ctxs[tid] = 0.f;
            atomicAdd(&g_context[b * H_ + k0 + tid], v);
        }
        MBARRIER_WAIT_PARITY(smem_base + SM_MBAR, kc & 1);
        __syncthreads();
    }

    TCGEN05_FENCE_AFTER();

    // epilogue: TMEM -> padded smem slab -> fp16 half2-packed coalesced gmem
    float* slab = (float*)(smem + SM_AHI);
    uint32_t* Cb = (uint32_t*)(g_hatt_h + ((size_t)b * L_ + l0) * A_);
    for (int cb = 0; cb < 4; cb++) {
        if (wid < 4) {
            uint32_t r[32];
            TCGEN05_LD_32X32B_X32(r, tmem_base + cb * 32);
            TCGEN05_WAIT_LD();
            const int row = wid * 32 + lid;
#pragma unroll
            for (int j = 0; j < 32; j++) slab[row * 33 + j] = __uint_as_float(r[j]);
        }
        __syncthreads();
#pragma unroll
        for (int it = 0; it < 8; it++) {
            const int idx = it * 256 + tid;
            const int row = idx >> 4;
            const int c2 = idx & 15;
            __half2 h = __floats2half2_rn(slab[row * 33 + c2 * 2], slab[row * 33 + c2 * 2 + 1]);
            Cb[(size_t)row * (A_ / 2) + cb * 16 + c2] = *(uint32_t*)&h;
        }
        __syncthreads();
    }

    TCGEN05_FENCE_BEFORE();
    if (tid == 0) MBARRIER_INVAL(smem_base + SM_MBAR);
    __syncthreads();
    if (wid == 0) TCGEN05_DEALLOC(tmem_base, 128);

#else  // ---------------- FFMA2 fallback ----------------
    float* As = (float*)smem;
    float* Bs = As + KCH * 128;

    const int tile = blockIdx.x;
    const int b = blockIdx.y;
    const int l0 = tile * 128;
    const int tid = threadIdx.x;
    const int tx = tid & 15, ty = tid >> 4;
    const int c0 = tx * 8, r0 = ty * 8;

    unsigned long long acc[8][4];
#pragma unroll
    for (int i = 0; i < 8; i++)
#pragma unroll
        for (int j = 0; j < 4; j++) acc[i][j] = 0ULL;

    const float* Abase = hid + ((size_t)(b * L_ + l0)) * H_;

    for (int kc = 0; kc < H_ / KCH; kc++) {
        const int k0 = kc * KCH;
#pragma unroll
        for (int p = 0; p < 4; p++) {
            int f4 = p * 256 + tid;
            int row = f4 >> 3;
            int kq = f4 & 7;
            float4 v = *(const float4*)(Abase + (size_t)row * H_ + k0 + kq * 4);
            As[(kq * 4 + 0) * 128 + row] = v.x;
            As[(kq * 4 + 1) * 128 + row] = v.y;
            As[(kq * 4 + 2) * 128 + row] = v.z;
            As[(kq * 4 + 3) * 128 + row] = v.w;
        }
#pragma unroll
        for (int p = 0; p < 4; p++) {
            int f4 = p * 256 + tid;
            int kk = f4 >> 5;
            int c4 = f4 & 31;
            *(float4*)&Bs[kk * 128 + c4 * 4] = *(const float4*)(W + (size_t)(k0 + kk) * A_ + c4 * 4);
        }
        __syncthreads();

        if (tid < 32) {
            float s = 0.f;
#pragma unroll 8
            for (int r = 0; r < 128; r++) s += As[tid * 128 + ((r + tid) & 127)];
            atomicAdd(&g_context[b * H_ + k0 + tid], s);
        }

#pragma unroll 8
        for (int kk = 0; kk < KCH; kk++) {
            float4 a0 = *(const float4*)&As[kk * 128 + r0];
            float4 a1 = *(const float4*)&As[kk * 128 + r0 + 4];
            ulonglong2 b01 = *(const ulonglong2*)&Bs[kk * 128 + c0];
            ulonglong2 b23 = *(const ulonglong2*)&Bs[kk * 128 + c0 + 4];
            unsigned long long bb0 = b01.x, bb1 = b01.y, bb2 = b23.x, bb3 = b23.y;
            float av[8] = {a0.x, a0.y, a0.z, a0.w, a1.x, a1.y, a1.z, a1.w};
#pragma unroll
            for (int i = 0; i < 8; i++) {
                unsigned long long ap = pack2(av[i], av[i]);
                FMA2(acc[i][0], ap, bb0);
                FMA2(acc[i][1], ap, bb1);
                FMA2(acc[i][2], ap, bb2);
                FMA2(acc[i][3], ap, bb3);
            }
        }
        __syncthreads();
    }

    __half* Cbase = g_hatt_h + ((size_t)(b * L_ + l0 + r0)) * A_ + c0;
#pragma unroll
    for (int i = 0; i < 8; i++) {
        float o[8];
#pragma unroll
        for (int j = 0; j < 4; j++) unpack2(acc[i][j], o[2 * j], o[2 * j + 1]);
#pragma unroll
        for (int j = 0; j < 8; j++) Cbase[(size_t)i * A_ + j] = __float2half_rn(o[j]);
    }
#endif
}

// ---------------- kernel 2: u[b][a] = (mean context) @ U_a ----------------
__global__ __launch_bounds__(512) void k_uatt(const float* __restrict__ U) {
    const int b = blockIdx.x;
    const int tid = threadIdx.x;
    const int a = tid & 127;
    const int q = tid >> 7;
    __shared__ float c[H_];
    __shared__ float part[4][128];
    c[tid] = g_context[b * H_ + tid] * (1.f / (float)L_);
    __syncthreads();
    const float* Up = U + (size_t)(q * 128) * A_ + a;
    const float* cp = c + q * 128;
    float s0 = 0.f, s1 = 0.f, s2 = 0.f, s3 = 0.f;
#pragma unroll 8
    for (int hh = 0; hh < 128; hh += 4) {
        s0 += cp[hh] * Up[(size_t)hh * A_];
        s1 += cp[hh + 1] * Up[(size_t)(hh + 1) * A_];
        s2 += cp[hh + 2] * Up[(size_t)(hh + 2) * A_];
        s3 += cp[hh + 3] * Up[(size_t)(hh + 3) * A_];
    }
    part[q][a] = (s0 + s1) + (s2 + s3);
    __syncthreads();
    if (tid < 128) {
        g_u[b * A_ + tid] = (part[0][tid] + part[1][tid]) + (part[2][tid] + part[3][tid]);
    }
}

// ---------------- kernel 3: scores = v^T tanh_hw(hatt_fp16 + u) ----------------
// grid (32, 64): 64 rows/block, 8 warps x 8 rows, hraw[8] -> low regs, high occupancy
__global__ __launch_bounds__(256) void k_scores(const float* __restrict__ va) {
    __shared__ float su[A_], sv[A_];
    const int tile = blockIdx.x, b = blockIdx.y;
    const int tid = threadIdx.x;
    if (tid < A_) {
        su[tid] = g_u[b * A_ + tid];
        sv[tid] = va[tid];
    }
    __syncthreads();
    const int w = tid >> 5, lane = tid & 31;
    const float4 u4 = *(const float4*)&su[lane * 4];
    const float4 v4 = *(const float4*)&sv[lane * 4];

    // front-batch 8 row-loads (MLP=8 per thread; 2x blocks vs R14 keeps total MLP)
    uint2 hraw[8];
    const int l0 = tile * 64 + w * 8;
    const uint32_t* base =
        (const uint32_t*)(g_hatt_h + ((size_t)(b * L_ + l0)) * A_) + lane * 2;
#pragma unroll
    for (int t = 0; t < 8; t++)
        hraw[t] = *(const uint2*)(base + (size_t)t * (A_ / 2));

#pragma unroll
    for (int t = 0; t < 8; t++) {
        const float2 h01 = __half22float2(*(const __half2*)&hraw[t].x);
        const float2 h23 = __half22float2(*(const __half2*)&hraw[t].y);
        float s = v4.x * tanh_hw(h01.x + u4.x) + v4.y * tanh_hw(h01.y + u4.y) +
                  v4.z * tanh_hw(h23.x + u4.z) + v4.w * tanh_hw(h23.y + u4.w);
#pragma unroll
        for (int o = 16; o; o >>= 1) s += __shfl_down_sync(0xffffffffu, s, o);
        if (lane == 0) g_scores[b * L_ + l0 + t] = s;
    }
}

// ---------------- kernel 4: softmax over L, write attn to d_out ----------------
__global__ void k_softmax(float* __restrict__ attn_out) {
    const int b = blockIdx.x;
    const int tid = threadIdx.x;
    __shared__ float red[256];
    float vals[8];
    float m = -1e30f;
#pragma unroll
    for (int i = 0; i < 8; i++) {
        vals[i] = g_scores[b * L_ + tid + 256 * i];
        m = fmaxf(m, vals[i]);
    }
    red[tid] = m;
    __syncthreads();
    for (int o = 128; o; o >>= 1) {
        if (tid < o) red[tid] = fmaxf(red[tid], red[tid + o]);
        __syncthreads();
    }
    m = red[0];
    __syncthreads();
    float sum = 0.f;
#pragma unroll
    for (int i = 0; i < 8; i++) {
        vals[i] = __expf(vals[i] - m);
        sum += vals[i];
    }
    red[tid] = sum;
    __syncthreads();
    for (int o = 128; o; o >>= 1) {
        if (tid < o) red[tid] += red[tid + o];
        __syncthreads();
    }
    const float inv = 1.f / red[0];
#pragma unroll
    for (int i = 0; i < 8; i++) attn_out[b * L_ + tid + 256 * i] = vals[i] * inv;
}

// ---------------- kernel 5: attended ----------------
__global__ __launch_bounds__(512) void k_attended(const float* __restrict__ hid,
                                                  const float* __restrict__ attn) {
    const int tile = blockIdx.x, b = blockIdx.y;
    const int tid = threadIdx.x;
    const int g = tid >> 7;
    const int h4 = tid & 127;
    __shared__ float sa[128];
    __shared__ float4 comb[4][128];
    if (tid < 128) sa[tid] = attn[b * L_ + tile * 128 + tid];
    __syncthreads();
    const float4* hp = (const float4*)(hid + ((size_t)(b * L_) + tile * 128 + g * 32) * H_) + h4;
    const float* sap = sa + g * 32;
    float4 acc = {0.f, 0.f, 0.f, 0.f};
#pragma unroll 4
    for (int l = 0; l < 32; l++) {
        const float w = sap[l];
        const float4 v = hp[(size_t)l * (H_ / 4)];
        acc.x += w * v.x;
        acc.y += w * v.y;
        acc.z += w * v.z;
        acc.w += w * v.w;
    }
    comb[g][h4] = acc;
    __syncthreads();
    if (tid < 128) {
        float4 a0 = comb[0][tid], a1 = comb[1][tid], a2 = comb[2][tid], a3 = comb[3][tid];
        float* dst = &g_attended[b * H_ + tid * 4];
        atomicAdd(dst + 0, (a0.x + a1.x) + (a2.x + a3.x));
        atomicAdd(dst + 1, (a0.y + a1.y) + (a2.y + a3.y));
        atomicAdd(dst + 2, (a0.z + a1.z) + (a2.z + a3.z));
        atomicAdd(dst + 3, (a0.w + a1.w) + (a2.w + a3.w));
    }
}

// ---------------- kernel 6: LayerNorm ----------------
__global__ __launch_bounds__(512) void k_ln(const float* __restrict__ gamma,
                                            const float* __restrict__ beta,
                                            float* __restrict__ out) {
    const int b = blockIdx.x;
    const int h = threadIdx.x;
    __shared__ float red[512];
    float x = g_attended[b * H_ + h];
    red[h] = x;
    __syncthreads();
    for (int o = 256; o; o >>= 1) {
        if (h < o) red[h] += red[h + o];
        __syncthreads();
    }
    const float mu = red[0] * (1.f / (float)H_);
    __syncthreads();
    const float d = x - mu;
    red[h] = d * d;
    __syncthreads();
    for (int o = 256; o; o >>= 1) {
        if (h < o) red[h] += red[h + o];
        __syncthreads();
    }
    const float var = red[0] * (1.f / (float)H_);
    out[b * H_ + h] = d * rsqrtf(var + LN_EPS) * gamma[h] + beta[h];
}

extern "C" void kernel_launch(void* const* d_in, const int* in_sizes, int n_in,
                              void* d_out, int out_size) {
    const float* hid = (const float*)d_in[0];
    const float* W = (const float*)d_in[1];
    const float* U = (const float*)d_in[2];
    const float* va = (const float*)d_in[3];
    const float* gamma = (const float*)d_in[4];
    const float* beta = (const float*)d_in[5];
    (void)in_sizes; (void)n_in; (void)out_size;

    float* out = (float*)d_out;
    float* attn = out + B_ * H_;

    cudaFuncSetAttribute(k_gemm, cudaFuncAttributeMaxDynamicSharedMemorySize, SM_TOTAL);

    k_prep<<<256, 256>>>(W);
    k_gemm<<<dim3(16, 64), 256, SM_TOTAL>>>(hid, W);
    k_uatt<<<B_, 512>>>(U);
    k_scores<<<dim3(32, 64), 256>>>(va);
    k_softmax<<<B_, 256>>>(attn);
    k_attended<<<dim3(16, 64), 512>>>(hid, attn);
    k_ln<<<B_, 512>>>(gamma, beta, out);
}